// round 16
// baseline (speedup 1.0000x reference)
#include <cuda_runtime.h>
#include <cuda_fp16.h>
#include <cstdint>

#define D        128
#define BLK      1024
#define THREADS  256
#define NROWS    262144

// w = ex2(min(S*C2 + ci + cj, 0)), ci = -||xi||^2*log2e/25.6 (pre-scaled in prep)
#define C2       0.11271055f
#define SQSCALE  (-0.056355275f)

// ---- smem: XOR-swizzled 256B-row tiles ----
#define OFF_XIH  0                     // 64 x 256 = 16K
#define OFF_W    16384                 // 64 x 256 = 16K
#define OFF_XJ   32768                 // 2 x XjH (32K each)
#define BUF_SZ   32768
#define SM_TOTAL (OFF_XJ + 2 * BUF_SZ) // 98304 -> 2 CTAs/SM

// ---------------- global scratch ----------------
__device__ float   g_sq[NROWS];
__device__ __half  g_xhi[(size_t)NROWS * D];

// ---------------- PTX helpers ----------------
__device__ __forceinline__ uint32_t smem_u32(const void* p) {
    uint32_t a;
    asm("{ .reg .u64 t; cvta.to.shared.u64 t, %1; cvt.u32.u64 %0, t; }" : "=r"(a) : "l"(p));
    return a;
}
__device__ __forceinline__ void cpa16(uint32_t dst, const void* src) {
    asm volatile("cp.async.cg.shared.global [%0], [%1], 16;" :: "r"(dst), "l"(src));
}
#define CP_COMMIT() asm volatile("cp.async.commit_group;" ::: "memory")
#define CP_WAIT0()  asm volatile("cp.async.wait_group 0;" ::: "memory")
#define BAR_SYNC(id, n)   asm volatile("bar.sync %0, %1;"   :: "n"(id), "n"(n) : "memory")
#define BAR_ARRIVE(id, n) asm volatile("bar.arrive %0, %1;" :: "n"(id), "n"(n) : "memory")

__device__ __forceinline__ void ldsm4(uint32_t r[4], uint32_t addr) {
    asm volatile("ldmatrix.sync.aligned.m8n8.x4.shared.b16 {%0,%1,%2,%3}, [%4];"
                 : "=r"(r[0]), "=r"(r[1]), "=r"(r[2]), "=r"(r[3]) : "r"(addr));
}
__device__ __forceinline__ void ldsm4t(uint32_t r[4], uint32_t addr) {
    asm volatile("ldmatrix.sync.aligned.m8n8.x4.trans.shared.b16 {%0,%1,%2,%3}, [%4];"
                 : "=r"(r[0]), "=r"(r[1]), "=r"(r[2]), "=r"(r[3]) : "r"(addr));
}
__device__ __forceinline__ void mma16816(float c[4], const uint32_t a[4],
                                         uint32_t b0, uint32_t b1) {
    asm volatile("mma.sync.aligned.m16n8k16.row.col.f32.f16.f16.f32 "
                 "{%0,%1,%2,%3}, {%4,%5,%6,%7}, {%8,%9}, {%0,%1,%2,%3};"
                 : "+f"(c[0]), "+f"(c[1]), "+f"(c[2]), "+f"(c[3])
                 : "r"(a[0]), "r"(a[1]), "r"(a[2]), "r"(a[3]), "r"(b0), "r"(b1));
}
__device__ __forceinline__ float ex2(float e) {
    float r;
    asm("ex2.approx.f32 %0, %1;" : "=f"(r) : "f"(e));
    return r;
}
__device__ __forceinline__ uint32_t h2u(__half2 h) {
    return *reinterpret_cast<uint32_t*>(&h);
}

// ---------------------------------------------------------------------------
// Prepass: fp32 -> fp16 + pre-scaled row norms. One warp per row.
// ---------------------------------------------------------------------------
__global__ __launch_bounds__(256) void prep_kernel(const float4* __restrict__ x) {
    int row = blockIdx.x * 8 + (threadIdx.x >> 5);
    int l   = threadIdx.x & 31;
    float4 v = __ldg(&x[(size_t)row * 32 + l]);
    float s = v.x * v.x + v.y * v.y + v.z * v.z + v.w * v.w;
    #pragma unroll
    for (int o = 16; o; o >>= 1) s += __shfl_xor_sync(0xFFFFFFFFu, s, o);
    if (l == 0) g_sq[row] = s * SQSCALE;
    __half2 h01 = __floats2half2_rn(v.x, v.y);
    __half2 h23 = __floats2half2_rn(v.z, v.w);
    ((uint2*)g_xhi)[(size_t)row * 32 + l] = make_uint2(h2u(h01), h2u(h23));
}

// ---------------------------------------------------------------------------
// Fused attention, warp-specialized:
//   G1 (warps 0-3): GEMM1 (32i x 64j tiles) + exp epilogue -> W, Xj prefetch.
//   G2 (warps 4-7): GEMM2 (32i x 64d tiles) one j-tile behind, + output.
// Barriers: A(id1,256) W-full G1->G2; B(id2,256) round-done G2->G1;
//           id4(128) G1-local cp.async visibility.
// ---------------------------------------------------------------------------
__global__ __launch_bounds__(THREADS, 2)
void attn_kernel(float* __restrict__ out) {
    extern __shared__ char sm[];
    const uint32_t sb = smem_u32(sm);

    const int tid = threadIdx.x;
    const int wid = tid >> 5;
    const int l   = tid & 31;
    const int cta  = blockIdx.x;
    const int blkI = cta >> 4, isub = cta & 15;
    const size_t rowbase = (size_t)blkI * BLK;
    const size_t irow0   = rowbase + (size_t)isub * 64;

    const int ph  = l & 7;
    const int rph = (l >> 2) & 7;
    const int cA  = l >> 4;
    const int cB  = (l >> 3) & 1;

    const char* ghb = (const char*)(g_xhi + rowbase * D);

    // ---- prologue: all 256 threads load Xi + Xj(0) ----
    {
        const char* gih = (const char*)(g_xhi + irow0 * D);
        #pragma unroll
        for (int it = 0; it < 4; ++it) {
            int q = tid + it * 256;          // Xi: 1024 chunks
            int row = q >> 4, c16 = q & 15;
            uint32_t dsw = (uint32_t)((row << 8) + ((c16 ^ (row & 7)) << 4));
            cpa16(sb + OFF_XIH + dsw, gih + (size_t)q * 16);
        }
        #pragma unroll
        for (int it = 0; it < 8; ++it) {
            int q = tid + it * 256;          // Xj0: 2048 chunks
            int row = q >> 4, c16 = q & 15;
            uint32_t dsw = (uint32_t)((row << 8) + ((c16 ^ (row & 7)) << 4));
            cpa16(sb + OFF_XJ + dsw, ghb + (size_t)q * 16);
        }
        CP_COMMIT();
        CP_WAIT0();
        __syncthreads();
    }

    if (wid < 4) {
        // ================= G1: GEMM1 + epilogue + prefetch =================
        const int wm1 = wid >> 1, wn1 = wid & 1;
        const uint32_t aRow  = (uint32_t)((32 * wm1 + (l & 15)) << 8);
        const uint32_t b1Row = (uint32_t)((64 * wn1 + (l & 7) + ((l >> 4) << 3)) << 8);
        const int tg = tid;                  // 0..127

        float civ[2][2];
        #pragma unroll
        for (int mt = 0; mt < 2; ++mt) {
            civ[mt][0] = __ldg(&g_sq[irow0 + 32 * wm1 + 16 * mt + (l >> 2)]);
            civ[mt][1] = __ldg(&g_sq[irow0 + 32 * wm1 + 16 * mt + 8 + (l >> 2)]);
        }

        for (int jt = 0; jt < 8; ++jt) {
            const uint32_t XJH = sb + OFF_XJ + (uint32_t)(jt & 1) * BUF_SZ;

            CP_WAIT0();          // Xj(jt) landed (issued by G1 last round)
            BAR_SYNC(4, 128);    // G1-internal visibility

            // ---- GEMM1: 32i x 64j per warp, 1 combo ----
            float acc1[2][8][4];
            #pragma unroll
            for (int mt = 0; mt < 2; ++mt)
                #pragma unroll
                for (int n = 0; n < 8; ++n)
                    #pragma unroll
                    for (int c = 0; c < 4; ++c) acc1[mt][n][c] = 0.0f;

            #pragma unroll
            for (int ks = 0; ks < 8; ++ks) {
                const uint32_t ca = (uint32_t)(((2 * ks + cA) ^ ph) << 4);
                const uint32_t cb = (uint32_t)(((2 * ks + cB) ^ ph) << 4);
                uint32_t ah[2][4];
                #pragma unroll
                for (int mt = 0; mt < 2; ++mt)
                    ldsm4(ah[mt], sb + OFF_XIH + aRow + mt * 4096 + ca);
                #pragma unroll
                for (int nt2 = 0; nt2 < 4; ++nt2) {
                    uint32_t bh[4];
                    ldsm4(bh, XJH + b1Row + nt2 * 4096 + cb);
                    #pragma unroll
                    for (int mt = 0; mt < 2; ++mt) {
                        mma16816(acc1[mt][2 * nt2],     ah[mt], bh[0], bh[1]);
                        mma16816(acc1[mt][2 * nt2 + 1], ah[mt], bh[2], bh[3]);
                    }
                }
            }

            if (jt > 0) BAR_SYNC(2, 256);    // B: G2 drained W(jt-1) + Xj(jt-1)

            // ---- epilogue: w -> W tile ----
            {
                const float2* cjp = (const float2*)(g_sq + rowbase + (size_t)jt * 128);
                #pragma unroll
                for (int n = 0; n < 8; ++n) {
                    float2 cj = __ldg(&cjp[32 * wn1 + 4 * n + (l & 3)]);
                    const uint32_t wcol = (uint32_t)((((8 * wn1 + n) ^ rph) << 4) + ((l & 3) << 2));
                    #pragma unroll
                    for (int mt = 0; mt < 2; ++mt) {
                        const float* c = acc1[mt][n];
                        float w0 = ex2(fminf(fmaf(c[0], C2, civ[mt][0] + cj.x), 0.0f));
                        float w1 = ex2(fminf(fmaf(c[1], C2, civ[mt][0] + cj.y), 0.0f));
                        float w2 = ex2(fminf(fmaf(c[2], C2, civ[mt][1] + cj.x), 0.0f));
                        float w3 = ex2(fminf(fmaf(c[3], C2, civ[mt][1] + cj.y), 0.0f));
                        const uint32_t wr = (uint32_t)((32 * wm1 + 16 * mt + (l >> 2)) << 8);
                        *(uint32_t*)(sm + OFF_W + wr + wcol)        = h2u(__floats2half2_rn(w0, w1));
                        *(uint32_t*)(sm + OFF_W + wr + 2048 + wcol) = h2u(__floats2half2_rn(w2, w3));
                    }
                }
            }
            BAR_ARRIVE(1, 256);              // A: W(jt) full

            // ---- prefetch Xj(jt+1) (safe: G2 done with target buffer) ----
            if (jt < 7) {
                uint32_t PH = sb + OFF_XJ + (uint32_t)((jt + 1) & 1) * BUF_SZ;
                const char* gsrc = ghb + (size_t)(jt + 1) * 32768;
                #pragma unroll
                for (int it = 0; it < 16; ++it) {
                    int q = tg + it * 128;
                    int row = q >> 4, c16 = q & 15;
                    uint32_t dsw = (uint32_t)((row << 8) + ((c16 ^ (row & 7)) << 4));
                    cpa16(PH + dsw, gsrc + (size_t)q * 16);
                }
                CP_COMMIT();
            }
        }
    } else {
        // ================= G2: GEMM2 + output =================
        const int wm2 = (wid - 4) >> 1, wd = (wid - 4) & 1;
        const uint32_t wRow  = (uint32_t)((32 * wm2 + (l & 15)) << 8);
        const uint32_t b2Row = (uint32_t)((l & 15) << 8);

        float acc2[2][8][4];
        #pragma unroll
        for (int mt = 0; mt < 2; ++mt)
            #pragma unroll
            for (int n = 0; n < 8; ++n)
                #pragma unroll
                for (int c = 0; c < 4; ++c) acc2[mt][n][c] = 0.0f;

        for (int jt = 0; jt < 8; ++jt) {
            const uint32_t XJH = sb + OFF_XJ + (uint32_t)(jt & 1) * BUF_SZ;

            BAR_SYNC(1, 256);                // A: W(jt) ready

            // ---- GEMM2: 32i x 64d per warp, 1 combo, K=128 ----
            #pragma unroll
            for (int ks = 0; ks < 8; ++ks) {
                const uint32_t ca = (uint32_t)(((2 * ks + cA) ^ ph) << 4);
                uint32_t wh[2][4];
                #pragma unroll
                for (int mt = 0; mt < 2; ++mt)
                    ldsm4(wh[mt], sb + OFF_W + wRow + mt * 4096 + ca);
                #pragma unroll
                for (int dp = 0; dp < 4; ++dp) {
                    const uint32_t cb2 = (uint32_t)(((8 * wd + 2 * dp + cA) ^ ph) << 4);
                    uint32_t bh[4];
                    ldsm4t(bh, XJH + b2Row + ks * 4096 + cb2);
                    #pragma unroll
                    for (int mt = 0; mt < 2; ++mt) {
                        mma16816(acc2[mt][2 * dp],     wh[mt], bh[0], bh[1]);
                        mma16816(acc2[mt][2 * dp + 1], wh[mt], bh[2], bh[3]);
                    }
                }
            }

            if (jt < 7) BAR_ARRIVE(2, 256);  // B: W + Xj(jt) drained
        }

        // ---- output (scale 1/1024) ----
        const float sc = 1.0f / (float)BLK;
        #pragma unroll
        for (int mt = 0; mt < 2; ++mt) {
            const size_t r0 = irow0 + 32 * wm2 + 16 * mt + (l >> 2);
            #pragma unroll
            for (int n = 0; n < 8; ++n) {
                const int col = 64 * wd + 8 * n + 2 * (l & 3);
                *(float2*)(out + r0 * D + col)       = make_float2(acc2[mt][n][0] * sc, acc2[mt][n][1] * sc);
                *(float2*)(out + (r0 + 8) * D + col) = make_float2(acc2[mt][n][2] * sc, acc2[mt][n][3] * sc);
            }
        }
    }
}

// ---------------------------------------------------------------------------
extern "C" void kernel_launch(void* const* d_in, const int* in_sizes, int n_in,
                              void* d_out, int out_size) {
    const float* x = (const float*)d_in[0];
    float* out = (float*)d_out;
    const int nrows = in_sizes[0] / D;

    static bool attr_set = false;
    if (!attr_set) {
        cudaFuncSetAttribute(attn_kernel,
                             cudaFuncAttributeMaxDynamicSharedMemorySize, SM_TOTAL);
        attr_set = true;
    }
    prep_kernel<<<nrows / 8, 256>>>((const float4*)x);
    attn_kernel<<<nrows / 64, THREADS, SM_TOTAL>>>(out);
}

// round 17
// speedup vs baseline: 1.0019x; 1.0019x over previous
#include <cuda_runtime.h>
#include <cuda_fp16.h>
#include <cstdint>

#define D        128
#define BLK      1024
#define THREADS  256
#define NROWS    262144

// w = ex2(min(S*C2 + ci + cj, 0)), ci = -||xi||^2*log2e/25.6 (pre-scaled in prep)
#define C2       0.11271055f
#define SQSCALE  (-0.056355275f)

// ---- smem: XOR-swizzled 256B-row tiles, 32KB each ----
#define OFF_XIH  0                      // 128 x 256
#define OFF_W0   32768
#define OFF_W1   65536
#define OFF_XJ   98304                  // 3 x 32K ring
#define SM_TOTAL (OFF_XJ + 3 * 32768)   // 196608 -> 1 CTA/SM

// ---------------- global scratch ----------------
__device__ float   g_sq[NROWS];
__device__ __half  g_xhi[(size_t)NROWS * D];

// ---------------- PTX helpers ----------------
__device__ __forceinline__ uint32_t smem_u32(const void* p) {
    uint32_t a;
    asm("{ .reg .u64 t; cvta.to.shared.u64 t, %1; cvt.u32.u64 %0, t; }" : "=r"(a) : "l"(p));
    return a;
}
__device__ __forceinline__ void cpa16(uint32_t dst, const void* src) {
    asm volatile("cp.async.cg.shared.global [%0], [%1], 16;" :: "r"(dst), "l"(src));
}
#define CP_COMMIT() asm volatile("cp.async.commit_group;" ::: "memory")
#define CP_WAIT0()  asm volatile("cp.async.wait_group 0;" ::: "memory")

__device__ __forceinline__ void ldsm4(uint32_t r[4], uint32_t addr) {
    asm volatile("ldmatrix.sync.aligned.m8n8.x4.shared.b16 {%0,%1,%2,%3}, [%4];"
                 : "=r"(r[0]), "=r"(r[1]), "=r"(r[2]), "=r"(r[3]) : "r"(addr));
}
__device__ __forceinline__ void ldsm4t(uint32_t r[4], uint32_t addr) {
    asm volatile("ldmatrix.sync.aligned.m8n8.x4.trans.shared.b16 {%0,%1,%2,%3}, [%4];"
                 : "=r"(r[0]), "=r"(r[1]), "=r"(r[2]), "=r"(r[3]) : "r"(addr));
}
__device__ __forceinline__ void mma16816(float c[4], const uint32_t a[4],
                                         uint32_t b0, uint32_t b1) {
    asm volatile("mma.sync.aligned.m16n8k16.row.col.f32.f16.f16.f32 "
                 "{%0,%1,%2,%3}, {%4,%5,%6,%7}, {%8,%9}, {%0,%1,%2,%3};"
                 : "+f"(c[0]), "+f"(c[1]), "+f"(c[2]), "+f"(c[3])
                 : "r"(a[0]), "r"(a[1]), "r"(a[2]), "r"(a[3]), "r"(b0), "r"(b1));
}
__device__ __forceinline__ float ex2(float e) {
    float r;
    asm("ex2.approx.f32 %0, %1;" : "=f"(r) : "f"(e));
    return r;
}
__device__ __forceinline__ uint32_t h2u(__half2 h) {
    return *reinterpret_cast<uint32_t*>(&h);
}

// ---------------------------------------------------------------------------
// Prepass: fp32 -> fp16 + pre-scaled row norms. One warp per row.
// ---------------------------------------------------------------------------
__global__ __launch_bounds__(256) void prep_kernel(const float4* __restrict__ x) {
    int row = blockIdx.x * 8 + (threadIdx.x >> 5);
    int l   = threadIdx.x & 31;
    float4 v = __ldg(&x[(size_t)row * 32 + l]);
    float s = v.x * v.x + v.y * v.y + v.z * v.z + v.w * v.w;
    #pragma unroll
    for (int o = 16; o; o >>= 1) s += __shfl_xor_sync(0xFFFFFFFFu, s, o);
    if (l == 0) g_sq[row] = s * SQSCALE;
    __half2 h01 = __floats2half2_rn(v.x, v.y);
    __half2 h23 = __floats2half2_rn(v.z, v.w);
    ((uint2*)g_xhi)[(size_t)row * 32 + l] = make_uint2(h2u(h01), h2u(h23));
}

// cp.async a 128x128 fp16 tile into swizzled smem (chunk = c16 ^ (row&7))
__device__ __forceinline__ void issue_tile(uint32_t dst, const char* g, int tid) {
    #pragma unroll
    for (int it = 0; it < 8; ++it) {
        int q   = tid + it * 256;
        int row = q >> 4, c16 = q & 15;
        uint32_t dsw = (uint32_t)((row << 8) + ((c16 ^ (row & 7)) << 4));
        cpa16(dst + dsw, g + (size_t)q * 16);
    }
}

// ---------------------------------------------------------------------------
// Skewed fused pipeline: round jt runs GEMM1(jt) + GEMM2(jt-1) interleaved,
// then epilogue(jt) -> W[jt&1]. One __syncthreads per round.
// CTA = 128 i-rows, 1 CTA/SM; warp grid wm(0..3)=32i, wn(0..1)=64j/64d.
// ---------------------------------------------------------------------------
__global__ __launch_bounds__(THREADS, 1)
void attn_kernel(float* __restrict__ out) {
    extern __shared__ char sm[];
    const uint32_t sb = smem_u32(sm);

    const int tid = threadIdx.x;
    const int wid = tid >> 5;
    const int l   = tid & 31;
    const int wm  = wid >> 1;        // 0..3: rows [32wm, 32wm+32)
    const int wn  = wid & 1;         // 0..1: cols [64wn, 64wn+64)
    const int cta  = blockIdx.x;
    const int blkI = cta >> 3, isub = cta & 7;
    const size_t rowbase = (size_t)blkI * BLK;
    const size_t irow0   = rowbase + (size_t)isub * 128;

    const int ph  = l & 7;
    const int rph = (l >> 2) & 7;
    const int cA  = l >> 4;
    const int cB  = (l >> 3) & 1;

    const uint32_t aRow  = (uint32_t)((32 * wm + (l & 15)) << 8);                  // Xi / W A-style
    const uint32_t b1Row = (uint32_t)((64 * wn + (l & 7) + ((l >> 4) << 3)) << 8); // G1 B
    const uint32_t b2Row = (uint32_t)((l & 15) << 8);                              // G2 B trans

    const char* ghb = (const char*)(g_xhi + rowbase * D);

    // Xj ring base addresses
    const uint32_t XJ0 = sb + OFF_XJ;
    const uint32_t XJ1 = XJ0 + 32768;
    const uint32_t XJ2 = XJ1 + 32768;

    // ---- prologue: Xi + Xj(0) ----
    issue_tile(sb + OFF_XIH, (const char*)(g_xhi + irow0 * D), tid);
    issue_tile(XJ0, ghb, tid);
    CP_COMMIT();

    float civ[2][2];
    #pragma unroll
    for (int mt = 0; mt < 2; ++mt) {
        civ[mt][0] = __ldg(&g_sq[irow0 + 32 * wm + 16 * mt + (l >> 2)]);
        civ[mt][1] = __ldg(&g_sq[irow0 + 32 * wm + 16 * mt + 8 + (l >> 2)]);
    }

    float acc2[2][8][4];
    #pragma unroll
    for (int mt = 0; mt < 2; ++mt)
        #pragma unroll
        for (int n = 0; n < 8; ++n)
            #pragma unroll
            for (int c = 0; c < 4; ++c) acc2[mt][n][c] = 0.0f;

    CP_WAIT0();
    __syncthreads();

    uint32_t bufc = XJ0, bufp = XJ2, bufn = XJ1;   // cur / prev / next (rotate)

    for (int jt = 0; jt < 8; ++jt) {
        const uint32_t WCUR = sb + ((jt & 1) ? OFF_W1 : OFF_W0);
        const uint32_t WPRV = sb + ((jt & 1) ? OFF_W0 : OFF_W1);

        // prefetch Xj(jt+1) into bufn (freed by GEMM2(jt-2) before last sync)
        if (jt < 7) {
            issue_tile(bufn, ghb + (size_t)(jt + 1) * 32768, tid);
            CP_COMMIT();
        }

        // ---- fused ks loop: GEMM1(jt) + GEMM2(jt-1) ----
        float acc1[2][8][4];
        #pragma unroll
        for (int mt = 0; mt < 2; ++mt)
            #pragma unroll
            for (int n = 0; n < 8; ++n)
                #pragma unroll
                for (int c = 0; c < 4; ++c) acc1[mt][n][c] = 0.0f;

        #pragma unroll
        for (int ks = 0; ks < 8; ++ks) {
            const uint32_t ca = (uint32_t)(((2 * ks + cA) ^ ph) << 4);
            const uint32_t cb = (uint32_t)(((2 * ks + cB) ^ ph) << 4);
            // --- GEMM1 stream ---
            uint32_t ah[2][4];
            #pragma unroll
            for (int mt = 0; mt < 2; ++mt)
                ldsm4(ah[mt], sb + OFF_XIH + aRow + mt * 4096 + ca);
            #pragma unroll
            for (int nt2 = 0; nt2 < 4; ++nt2) {
                uint32_t bh[4];
                ldsm4(bh, bufc + b1Row + nt2 * 4096 + cb);
                #pragma unroll
                for (int mt = 0; mt < 2; ++mt) {
                    mma16816(acc1[mt][2 * nt2],     ah[mt], bh[0], bh[1]);
                    mma16816(acc1[mt][2 * nt2 + 1], ah[mt], bh[2], bh[3]);
                }
            }
            // --- GEMM2 stream (previous tile), independent ---
            if (jt > 0) {
                uint32_t wh[2][4];
                #pragma unroll
                for (int mt = 0; mt < 2; ++mt)
                    ldsm4(wh[mt], WPRV + aRow + mt * 4096 + ca);
                #pragma unroll
                for (int dp = 0; dp < 4; ++dp) {
                    const uint32_t cb2 = (uint32_t)(((8 * wn + 2 * dp + cA) ^ ph) << 4);
                    uint32_t bt[4];
                    ldsm4t(bt, bufp + b2Row + ks * 4096 + cb2);
                    #pragma unroll
                    for (int mt = 0; mt < 2; ++mt) {
                        mma16816(acc2[mt][2 * dp],     wh[mt], bt[0], bt[1]);
                        mma16816(acc2[mt][2 * dp + 1], wh[mt], bt[2], bt[3]);
                    }
                }
            }
        }

        // ---- epilogue(jt): w -> W[jt&1] ----
        {
            const float2* cjp = (const float2*)(g_sq + rowbase + (size_t)jt * 128);
            #pragma unroll
            for (int n = 0; n < 8; ++n) {
                float2 cj = __ldg(&cjp[32 * wn + 4 * n + (l & 3)]);
                const uint32_t wcol = (uint32_t)((((8 * wn + n) ^ rph) << 4) + ((l & 3) << 2));
                #pragma unroll
                for (int mt = 0; mt < 2; ++mt) {
                    const float* c = acc1[mt][n];
                    float w0 = ex2(fminf(fmaf(c[0], C2, civ[mt][0] + cj.x), 0.0f));
                    float w1 = ex2(fminf(fmaf(c[1], C2, civ[mt][0] + cj.y), 0.0f));
                    float w2 = ex2(fminf(fmaf(c[2], C2, civ[mt][1] + cj.x), 0.0f));
                    float w3 = ex2(fminf(fmaf(c[3], C2, civ[mt][1] + cj.y), 0.0f));
                    const uint32_t wr = (uint32_t)((32 * wm + 16 * mt + (l >> 2)) << 8);
                    *(uint32_t*)(sm + (WCUR - sb) + wr + wcol)        = h2u(__floats2half2_rn(w0, w1));
                    *(uint32_t*)(sm + (WCUR - sb) + wr + 2048 + wcol) = h2u(__floats2half2_rn(w2, w3));
                }
            }
        }

        if (jt < 7) CP_WAIT0();   // Xj(jt+1) landed
        __syncthreads();          // W(jt) full; Xj(jt-1) drained; ring rotate safe

        uint32_t t = bufp; bufp = bufc; bufc = bufn; bufn = t;
    }

    // ---- final GEMM2(7): W[1], Xj(7) (= bufp after last rotation) ----
    {
        const uint32_t WPRV = sb + OFF_W1;
        #pragma unroll
        for (int ks = 0; ks < 8; ++ks) {
            const uint32_t ca = (uint32_t)(((2 * ks + cA) ^ ph) << 4);
            uint32_t wh[2][4];
            #pragma unroll
            for (int mt = 0; mt < 2; ++mt)
                ldsm4(wh[mt], WPRV + aRow + mt * 4096 + ca);
            #pragma unroll
            for (int dp = 0; dp < 4; ++dp) {
                const uint32_t cb2 = (uint32_t)(((8 * wn + 2 * dp + cA) ^ ph) << 4);
                uint32_t bt[4];
                ldsm4t(bt, bufp + b2Row + ks * 4096 + cb2);
                #pragma unroll
                for (int mt = 0; mt < 2; ++mt) {
                    mma16816(acc2[mt][2 * dp],     wh[mt], bt[0], bt[1]);
                    mma16816(acc2[mt][2 * dp + 1], wh[mt], bt[2], bt[3]);
                }
            }
        }
    }

    // ---- write out (scale 1/1024) ----
    const float sc = 1.0f / (float)BLK;
    #pragma unroll
    for (int mt = 0; mt < 2; ++mt) {
        const size_t r0 = irow0 + 32 * wm + 16 * mt + (l >> 2);
        #pragma unroll
        for (int n = 0; n < 8; ++n) {
            const int col = 64 * wn + 8 * n + 2 * (l & 3);
            *(float2*)(out + r0 * D + col)       = make_float2(acc2[mt][n][0] * sc, acc2[mt][n][1] * sc);
            *(float2*)(out + (r0 + 8) * D + col) = make_float2(acc2[mt][n][2] * sc, acc2[mt][n][3] * sc);
        }
    }
}

// ---------------------------------------------------------------------------
extern "C" void kernel_launch(void* const* d_in, const int* in_sizes, int n_in,
                              void* d_out, int out_size) {
    const float* x = (const float*)d_in[0];
    float* out = (float*)d_out;
    const int nrows = in_sizes[0] / D;

    static bool attr_set = false;
    if (!attr_set) {
        cudaFuncSetAttribute(attn_kernel,
                             cudaFuncAttributeMaxDynamicSharedMemorySize, SM_TOTAL);
        attr_set = true;
    }
    prep_kernel<<<nrows / 8, 256>>>((const float4*)x);
    attn_kernel<<<nrows / 128, THREADS, SM_TOTAL>>>(out);
}